// round 7
// baseline (speedup 1.0000x reference)
#include <cuda_runtime.h>
#include <cuda_bf16.h>

#define TSEQ   2048
#define BATCH  4096
#define HDIM   32
#define STAGE  16
#define NSTAGE (TSEQ / STAGE)
#define NBMAX  4
#define NB28BLOCKS 100   // blocks carrying 28 rows; remaining 48 carry 27

typedef unsigned long long ull;

// ---------- packed f32x2 helpers ----------
__device__ __forceinline__ ull pack2(float lo, float hi) {
    ull r;
    asm("mov.b64 %0, {%1, %2};" : "=l"(r) : "f"(lo), "f"(hi));
    return r;
}
__device__ __forceinline__ void unpack2(ull v, float& lo, float& hi) {
    asm("mov.b64 {%0, %1}, %2;" : "=f"(lo), "=f"(hi) : "l"(v));
}
__device__ __forceinline__ ull ffma2(ull a, ull b, ull c) {
    ull d;
    asm("fma.rn.f32x2 %0, %1, %2, %3;" : "=l"(d) : "l"(a), "l"(b), "l"(c));
    return d;
}
__device__ __forceinline__ ull add2(ull a, ull b) {
    ull d;
    asm("add.rn.f32x2 %0, %1, %2;" : "=l"(d) : "l"(a), "l"(b));
    return d;
}
// duplicated store without pack MOVs
__device__ __forceinline__ void sts_dup(unsigned int saddr, float v) {
    asm volatile("st.shared.v2.f32 [%0], {%1, %1};" :: "r"(saddr), "f"(v));
}

// ---------- single-MUFU tanh (sm_75+) ----------
__device__ __forceinline__ float tanhf_fast(float x) {
    float y;
    asm("tanh.approx.f32 %0, %1;" : "=f"(y) : "f"(x));
    return y;
}
// sigmoid(x) = 0.5*tanh(x/2) + 0.5 ; the /2 pre-folded into weights+bias.
__device__ __forceinline__ float sig_from_half(float xh) {
    return fmaf(0.5f, tanhf_fast(xh), 0.5f);
}

// One warp processes NB batch rows through all 2048 steps.
// Lane j owns h-index j. Gates packed (i,f),(g,o) into f32x2; sigmoid rows
// pre-scaled by 0.5. W_hh fully register-resident (128 regs/lane).
// Row-sequential matvec (4 chains) + per-row activation; next-step affine
// computed BEFORE the step-end syncwarp.
template <int NB>
__device__ __forceinline__ void lstm_run(
    const float* __restrict__ x,
    const float* __restrict__ W_ih,
    const float* __restrict__ W_hh,
    const float* __restrict__ b_ih,
    const float* __restrict__ b_hh,
    float* __restrict__ out,
    ull (*hdup)[NBMAX][HDIM],        // [2][NBMAX][32] this warp's slice
    ull (*xdup)[STAGE][4],           // [NBMAX][STAGE][4]
    int row0, int lane)
{
    constexpr int NX = (NB * STAGE * 3 + 31) / 32;

    // PyTorch gate rows for this lane: i, f, g, o
    const int r0 = lane;             // i  (sigmoid -> 0.5)
    const int r1 = HDIM + lane;      // f  (sigmoid -> 0.5)
    const int r2 = 2 * HDIM + lane;  // g  (tanh    -> 1.0)
    const int r3 = 3 * HDIM + lane;  // o  (sigmoid -> 0.5)

    // ---- recurrent weights into registers, gate-pair packed ----
    ull wif[HDIM], wgo[HDIM];
#pragma unroll
    for (int k = 0; k < HDIM; k++) {
        wif[k] = pack2(0.5f * W_hh[r0 * HDIM + k], 0.5f * W_hh[r1 * HDIM + k]);
        wgo[k] = pack2(       W_hh[r2 * HDIM + k], 0.5f * W_hh[r3 * HDIM + k]);
    }
    // ---- input weights + combined bias ----
    ull wxif[3], wxgo[3];
#pragma unroll
    for (int i = 0; i < 3; i++) {
        wxif[i] = pack2(0.5f * W_ih[r0 * 3 + i], 0.5f * W_ih[r1 * 3 + i]);
        wxgo[i] = pack2(       W_ih[r2 * 3 + i], 0.5f * W_ih[r3 * 3 + i]);
    }
    const ull bias_if = pack2(0.5f * (b_ih[r0] + b_hh[r0]),
                              0.5f * (b_ih[r1] + b_hh[r1]));
    const ull bias_go = pack2(       (b_ih[r2] + b_hh[r2]),
                              0.5f * (b_ih[r3] + b_hh[r3]));

    // shared addresses for the duplicated h stores (per parity buffer)
    unsigned int hsts[2];
    hsts[0] = (unsigned int)__cvta_generic_to_shared(&hdup[0][0][lane]);
    hsts[1] = (unsigned int)__cvta_generic_to_shared(&hdup[1][0][lane]);

    float c[NB];
#pragma unroll
    for (int b = 0; b < NB; b++) {
        c[b] = 0.0f;
        hdup[0][b][lane] = 0ull;
    }

    // ---- stage 0 of x ----
#pragma unroll
    for (int it = 0; it < NX; it++) {
        int idx = it * 32 + lane;
        if (idx < NB * STAGE * 3) {
            int b   = idx / (STAGE * 3);
            int rem = idx % (STAGE * 3);
            float v = x[(size_t)(row0 + b) * TSEQ * 3 + rem];
            xdup[b][rem / 3][rem % 3] = pack2(v, v);
        }
    }
    __syncwarp();

    // ---- affine for step 0 ----
    ull aff_if[NB], aff_go[NB];
#pragma unroll
    for (int b = 0; b < NB; b++) {
        ulonglong2 x01 = *reinterpret_cast<const ulonglong2*>(&xdup[b][0][0]);
        ull x2 = xdup[b][0][2];
        aff_if[b] = ffma2(x01.x, wxif[0], ffma2(x01.y, wxif[1], ffma2(x2, wxif[2], bias_if)));
        aff_go[b] = ffma2(x01.x, wxgo[0], ffma2(x01.y, wxgo[1], ffma2(x2, wxgo[2], bias_go)));
    }

#pragma unroll 1
    for (int s = 0; s < NSTAGE; s++) {
        // ---- prefetch next stage's x into registers (hidden over 16 steps) ----
        float xr[NX];
        if (s + 1 < NSTAGE) {
#pragma unroll
            for (int it = 0; it < NX; it++) {
                int idx = it * 32 + lane;
                if (idx < NB * STAGE * 3) {
                    int b   = idx / (STAGE * 3);
                    int rem = idx % (STAGE * 3);
                    xr[it] = x[(size_t)(row0 + b) * TSEQ * 3
                               + (size_t)(s + 1) * STAGE * 3 + rem];
                }
            }
        }

#pragma unroll 1
        for (int tt = 0; tt < STAGE; tt++) {
            const int rb = tt & 1;
            const int wb = rb ^ 1;

            // ---- rows sequential: matvec(b) -> act(b) overlaps matvec(b+1) ----
#pragma unroll
            for (int b = 0; b < NB; b++) {
                ull aifA = aff_if[b], agoA = aff_go[b];
                ull aifB = 0ull,      agoB = 0ull;
#pragma unroll
                for (int kk = 0; kk < HDIM; kk += 4) {
                    ulonglong2 hd0 = *reinterpret_cast<const ulonglong2*>(&hdup[rb][b][kk]);
                    ulonglong2 hd1 = *reinterpret_cast<const ulonglong2*>(&hdup[rb][b][kk + 2]);
                    aifA = ffma2(wif[kk],     hd0.x, aifA);
                    agoA = ffma2(wgo[kk],     hd0.x, agoA);
                    aifB = ffma2(wif[kk + 1], hd0.y, aifB);
                    agoB = ffma2(wgo[kk + 1], hd0.y, agoB);
                    aifA = ffma2(wif[kk + 2], hd1.x, aifA);
                    agoA = ffma2(wgo[kk + 2], hd1.x, agoA);
                    aifB = ffma2(wif[kk + 3], hd1.y, aifB);
                    agoB = ffma2(wgo[kk + 3], hd1.y, agoB);
                }
                ull tif = add2(aifA, aifB);
                ull tgo = add2(agoA, agoB);

                float ih, fh, gp, oh;
                unpack2(tif, ih, fh);
                unpack2(tgo, gp, oh);
                float ig = sig_from_half(ih);
                float fg = sig_from_half(fh);
                float gg = tanhf_fast(gp);
                float og = sig_from_half(oh);
                c[b] = fmaf(fg, c[b], ig * gg);
                float hb = og * tanhf_fast(c[b]);
                sts_dup(hsts[wb] + b * (HDIM * 8), hb);
            }

            // ---- next step's affine (independent of h): issue before the sync ----
            if (tt < STAGE - 1) {
#pragma unroll
                for (int b = 0; b < NB; b++) {
                    ulonglong2 x01 = *reinterpret_cast<const ulonglong2*>(&xdup[b][tt + 1][0]);
                    ull x2 = xdup[b][tt + 1][2];
                    aff_if[b] = ffma2(x01.x, wxif[0], ffma2(x01.y, wxif[1], ffma2(x2, wxif[2], bias_if)));
                    aff_go[b] = ffma2(x01.x, wxgo[0], ffma2(x01.y, wxgo[1], ffma2(x2, wxgo[2], bias_go)));
                }
            }
            __syncwarp();   // h published before next step's reads
        }

        // ---- commit prefetched x, then affine for first step of next stage ----
        if (s + 1 < NSTAGE) {
#pragma unroll
            for (int it = 0; it < NX; it++) {
                int idx = it * 32 + lane;
                if (idx < NB * STAGE * 3) {
                    int b   = idx / (STAGE * 3);
                    int rem = idx % (STAGE * 3);
                    xdup[b][rem / 3][rem % 3] = pack2(xr[it], xr[it]);
                }
            }
            __syncwarp();
#pragma unroll
            for (int b = 0; b < NB; b++) {
                ulonglong2 x01 = *reinterpret_cast<const ulonglong2*>(&xdup[b][0][0]);
                ull x2 = xdup[b][0][2];
                aff_if[b] = ffma2(x01.x, wxif[0], ffma2(x01.y, wxif[1], ffma2(x2, wxif[2], bias_if)));
                aff_go[b] = ffma2(x01.x, wxgo[0], ffma2(x01.y, wxgo[1], ffma2(x2, wxgo[2], bias_go)));
            }
        }
    }

    // Last step (tt=15) wrote parity buffer 0.
#pragma unroll
    for (int b = 0; b < NB; b++) {
        float lo, hi;
        unpack2(hdup[0][b][lane], lo, hi);
        out[(size_t)(row0 + b) * HDIM + lane] = lo;
    }
}

// Row distribution within a block. wid%4 -> SMSP, so wid i pairs with wid i+4.
// 28-row blocks: NB = 4,4,4,4,3,3,3,3  -> every SMSP pair carries 4+3 = 7 rows.
// 27-row blocks: NB = 4,4,4,3,3,3,3,3  -> pairs 7,7,7,6.
__device__ __constant__ int NB28[8]  = {4, 4, 4, 4, 3, 3, 3, 3};
__device__ __constant__ int OFF28[8] = {0, 4, 8, 12, 16, 19, 22, 25};
__device__ __constant__ int NB27[8]  = {4, 4, 4, 3, 3, 3, 3, 3};
__device__ __constant__ int OFF27[8] = {0, 4, 8, 12, 15, 18, 21, 24};

// 148 blocks x 256 threads: one block per SM, 2 warps per SMSP with
// controlled pairing; single wave, zero tail.
__global__ void __launch_bounds__(256, 1)
lstm_kernel(const float* __restrict__ x,
            const float* __restrict__ W_ih,
            const float* __restrict__ W_hh,
            const float* __restrict__ b_ih,
            const float* __restrict__ b_hh,
            float* __restrict__ out)
{
    __shared__ __align__(16) ull hd[8][2][NBMAX][HDIM];
    __shared__ __align__(16) ull xd[8][NBMAX][STAGE][4];

    const int wid  = threadIdx.x >> 5;
    const int lane = threadIdx.x & 31;
    const int bid  = blockIdx.x;

    int row0, nb;
    if (bid < NB28BLOCKS) {
        row0 = bid * 28 + OFF28[wid];
        nb   = NB28[wid];
    } else {
        row0 = NB28BLOCKS * 28 + (bid - NB28BLOCKS) * 27 + OFF27[wid];
        nb   = NB27[wid];
    }

    if (nb == 4) {
        lstm_run<4>(x, W_ih, W_hh, b_ih, b_hh, out, hd[wid], xd[wid], row0, lane);
    } else {
        lstm_run<3>(x, W_ih, W_hh, b_ih, b_hh, out, hd[wid], xd[wid], row0, lane);
    }
}

extern "C" void kernel_launch(void* const* d_in, const int* in_sizes, int n_in,
                              void* d_out, int out_size)
{
    const float* x    = (const float*)d_in[0];
    const float* W_ih = (const float*)d_in[1];
    const float* W_hh = (const float*)d_in[2];
    const float* b_ih = (const float*)d_in[3];
    const float* b_hh = (const float*)d_in[4];
    float* out = (float*)d_out;

    lstm_kernel<<<148, 256>>>(x, W_ih, W_hh, b_ih, b_hh, out);
}

// round 8
// speedup vs baseline: 1.1557x; 1.1557x over previous
#include <cuda_runtime.h>
#include <cuda_bf16.h>

#define TSEQ   2048
#define BATCH  4096
#define HDIM   32
#define STAGE  16
#define NSTAGE (TSEQ / STAGE)
#define NBMAX  4
#define NB28BLOCKS 100   // blocks carrying 28 rows; remaining 48 carry 27

typedef unsigned long long ull;

// ---------- packed f32x2 helpers ----------
__device__ __forceinline__ ull pack2(float lo, float hi) {
    ull r;
    asm("mov.b64 %0, {%1, %2};" : "=l"(r) : "f"(lo), "f"(hi));
    return r;
}
__device__ __forceinline__ ull ffma2(ull a, ull b, ull c) {
    ull d;
    asm("fma.rn.f32x2 %0, %1, %2, %3;" : "=l"(d) : "l"(a), "l"(b), "l"(c));
    return d;
}

// ---------- single-MUFU tanh (sm_75+) ----------
__device__ __forceinline__ float tanhf_fast(float x) {
    float y;
    asm("tanh.approx.f32 %0, %1;" : "=f"(y) : "f"(x));
    return y;
}
// sigmoid(x) = 0.5*tanh(x/2) + 0.5 ; the /2 pre-folded into weights+bias.
__device__ __forceinline__ float sig_from_half(float xh) {
    return fmaf(0.5f, tanhf_fast(xh), 0.5f);
}

// One warp processes NB batch rows through all 2048 steps.
// Lane j owns h-index j; h lives in REGISTERS and is broadcast to all lanes
// per k via __shfl_sync — no smem h, no per-step barrier.
// Gates packed (i,f),(g,o) into f32x2; sigmoid rows pre-scaled by 0.5.
// W_hh fully register-resident (128 regs/lane).
template <int NB>
__device__ __forceinline__ void lstm_run(
    const float* __restrict__ x,
    const float* __restrict__ W_ih,
    const float* __restrict__ W_hh,
    const float* __restrict__ b_ih,
    const float* __restrict__ b_hh,
    float* __restrict__ out,
    ull (*xdup)[STAGE][4],           // [NBMAX][STAGE][4] this warp's x slice
    int row0, int lane)
{
    constexpr int NX = (NB * STAGE * 3 + 31) / 32;

    // PyTorch gate rows for this lane: i, f, g, o
    const int r0 = lane;             // i  (sigmoid -> 0.5)
    const int r1 = HDIM + lane;      // f  (sigmoid -> 0.5)
    const int r2 = 2 * HDIM + lane;  // g  (tanh    -> 1.0)
    const int r3 = 3 * HDIM + lane;  // o  (sigmoid -> 0.5)

    // ---- recurrent weights into registers, gate-pair packed ----
    ull wif[HDIM], wgo[HDIM];
#pragma unroll
    for (int k = 0; k < HDIM; k++) {
        wif[k] = pack2(0.5f * W_hh[r0 * HDIM + k], 0.5f * W_hh[r1 * HDIM + k]);
        wgo[k] = pack2(       W_hh[r2 * HDIM + k], 0.5f * W_hh[r3 * HDIM + k]);
    }
    // ---- input weights + combined bias ----
    ull wxif[3], wxgo[3];
#pragma unroll
    for (int i = 0; i < 3; i++) {
        wxif[i] = pack2(0.5f * W_ih[r0 * 3 + i], 0.5f * W_ih[r1 * 3 + i]);
        wxgo[i] = pack2(       W_ih[r2 * 3 + i], 0.5f * W_ih[r3 * 3 + i]);
    }
    const ull bias_if = pack2(0.5f * (b_ih[r0] + b_hh[r0]),
                              0.5f * (b_ih[r1] + b_hh[r1]));
    const ull bias_go = pack2(       (b_ih[r2] + b_hh[r2]),
                              0.5f * (b_ih[r3] + b_hh[r3]));

    float c[NB], h[NB];
#pragma unroll
    for (int b = 0; b < NB; b++) { c[b] = 0.0f; h[b] = 0.0f; }

    // ---- stage 0 of x ----
#pragma unroll
    for (int it = 0; it < NX; it++) {
        int idx = it * 32 + lane;
        if (idx < NB * STAGE * 3) {
            int b   = idx / (STAGE * 3);
            int rem = idx % (STAGE * 3);
            float v = x[(size_t)(row0 + b) * TSEQ * 3 + rem];
            xdup[b][rem / 3][rem % 3] = pack2(v, v);
        }
    }
    __syncwarp();

#pragma unroll 1
    for (int s = 0; s < NSTAGE; s++) {
        // ---- prefetch next stage's x into registers (hidden over 16 steps) ----
        float xr[NX];
        if (s + 1 < NSTAGE) {
#pragma unroll
            for (int it = 0; it < NX; it++) {
                int idx = it * 32 + lane;
                if (idx < NB * STAGE * 3) {
                    int b   = idx / (STAGE * 3);
                    int rem = idx % (STAGE * 3);
                    xr[it] = x[(size_t)(row0 + b) * TSEQ * 3
                               + (size_t)(s + 1) * STAGE * 3 + rem];
                }
            }
        }

#pragma unroll 1
        for (int tt = 0; tt < STAGE; tt++) {
            // ---- input affine + bias (broadcast LDS from xdup) ----
            ull aif[NB], ago[NB];
#pragma unroll
            for (int b = 0; b < NB; b++) {
                ulonglong2 x01 = *reinterpret_cast<const ulonglong2*>(&xdup[b][tt][0]);
                ull x2 = xdup[b][tt][2];
                aif[b] = ffma2(x01.x, wxif[0], ffma2(x01.y, wxif[1], ffma2(x2, wxif[2], bias_if)));
                ago[b] = ffma2(x01.x, wxgo[0], ffma2(x01.y, wxgo[1], ffma2(x2, wxgo[2], bias_go)));
            }

            // ---- recurrent matvec: h broadcast via shfl, 2*NB chains ----
#pragma unroll
            for (int kk = 0; kk < HDIM; kk++) {
#pragma unroll
                for (int b = 0; b < NB; b++) {
                    float hk = __shfl_sync(0xffffffffu, h[b], kk);
                    ull hp = pack2(hk, hk);
                    aif[b] = ffma2(hp, wif[kk], aif[b]);
                    ago[b] = ffma2(hp, wgo[kk], ago[b]);
                }
            }

            // ---- activations + state update (i,f,o preacts pre-halved) ----
#pragma unroll
            for (int b = 0; b < NB; b++) {
                float2 vif = *reinterpret_cast<float2*>(&aif[b]);
                float2 vgo = *reinterpret_cast<float2*>(&ago[b]);
                float ig = sig_from_half(vif.x);
                float fg = sig_from_half(vif.y);
                float gg = tanhf_fast(vgo.x);
                float og = sig_from_half(vgo.y);
                c[b] = fmaf(fg, c[b], ig * gg);
                h[b] = og * tanhf_fast(c[b]);
            }
            // no barrier: recurrence carried entirely in registers via shfl
        }

        // ---- commit prefetched x ----
        if (s + 1 < NSTAGE) {
            __syncwarp();   // all lanes done reading stage s (affine LDS)
#pragma unroll
            for (int it = 0; it < NX; it++) {
                int idx = it * 32 + lane;
                if (idx < NB * STAGE * 3) {
                    int b   = idx / (STAGE * 3);
                    int rem = idx % (STAGE * 3);
                    xdup[b][rem / 3][rem % 3] = pack2(xr[it], xr[it]);
                }
            }
            __syncwarp();   // writes visible to all lanes
        }
    }

#pragma unroll
    for (int b = 0; b < NB; b++)
        out[(size_t)(row0 + b) * HDIM + lane] = h[b];
}

// Row distribution within a block. wid%4 -> SMSP, so wid i pairs with wid i+4.
// 28-row blocks: NB = 4,4,4,4,3,3,3,3  -> every SMSP pair carries 4+3 = 7 rows.
// 27-row blocks: NB = 4,4,4,3,3,3,3,3  -> pairs 7,7,7,6.
__device__ __constant__ int NB28[8]  = {4, 4, 4, 4, 3, 3, 3, 3};
__device__ __constant__ int OFF28[8] = {0, 4, 8, 12, 16, 19, 22, 25};
__device__ __constant__ int NB27[8]  = {4, 4, 4, 3, 3, 3, 3, 3};
__device__ __constant__ int OFF27[8] = {0, 4, 8, 12, 15, 18, 21, 24};

// 148 blocks x 256 threads: one block per SM, 2 warps per SMSP with
// controlled pairing; single wave, zero tail.
__global__ void __launch_bounds__(256, 1)
lstm_kernel(const float* __restrict__ x,
            const float* __restrict__ W_ih,
            const float* __restrict__ W_hh,
            const float* __restrict__ b_ih,
            const float* __restrict__ b_hh,
            float* __restrict__ out)
{
    __shared__ __align__(16) ull xd[8][NBMAX][STAGE][4];

    const int wid  = threadIdx.x >> 5;
    const int lane = threadIdx.x & 31;
    const int bid  = blockIdx.x;

    int row0, nb;
    if (bid < NB28BLOCKS) {
        row0 = bid * 28 + OFF28[wid];
        nb   = NB28[wid];
    } else {
        row0 = NB28BLOCKS * 28 + (bid - NB28BLOCKS) * 27 + OFF27[wid];
        nb   = NB27[wid];
    }

    if (nb == 4) {
        lstm_run<4>(x, W_ih, W_hh, b_ih, b_hh, out, xd[wid], row0, lane);
    } else {
        lstm_run<3>(x, W_ih, W_hh, b_ih, b_hh, out, xd[wid], row0, lane);
    }
}

extern "C" void kernel_launch(void* const* d_in, const int* in_sizes, int n_in,
                              void* d_out, int out_size)
{
    const float* x    = (const float*)d_in[0];
    const float* W_ih = (const float*)d_in[1];
    const float* W_hh = (const float*)d_in[2];
    const float* b_ih = (const float*)d_in[3];
    const float* b_hh = (const float*)d_in[4];
    float* out = (float*)d_out;

    lstm_kernel<<<148, 256>>>(x, W_ih, W_hh, b_ih, b_hh, out);
}